// round 12
// baseline (speedup 1.0000x reference)
#include <cuda_runtime.h>

// NURBS surface eval: DEG=3, N_CP=32x32, N_EVAL=2,000,000.
// Clamped-uniform knots: knot(i) = clamp(i-3,0,29)/29, span = floor(u*29)+3.
// Output: d_out[0..4N) = points (x,y,z,1); d_out[4N..8N) = normals (nx,ny,nz,0).
//
// R12 = R5 (champ: Cox-de Boor select-basis, 8x bank-column-replicated smem
// table, zero LDS conflicts) with the latency bottleneck removed:
//  * 512 threads/block -> 128-reg ceiling: ALL 16 gathered float4 cells are
//    hoisted into registers (16 LDS in flight, MLP=16) BEFORE the basis
//    computation, whose ~90 instructions hide the entire LDS latency
//    in-thread. Contraction is then a pure register FMA burst.
//    (At 1024 thr / 64 regs this is impossible - the compiler must chain
//    LDS->FMA serially; that chain was capping issue at 69.5%.)
//  * uv prefetched one grid-stride iteration ahead (LDG off the path).
// Partition of unity => homogeneous w == 1 (no divide). smem still caps
// occupancy at 1 block/SM, so warp loss is the deliberate price for MLP.

#define NCP 32
#define NTHREADS 512
#define NBLOCKS 148
#define TAB_BYTES (NCP * NCP * 8 * 16)   // 128 KB

__device__ __forceinline__ float rcp29(int m) {
    // 29/m for m in {1,2,3}
    return m == 1 ? 29.0f : (m == 2 ? 14.5f : (29.0f / 3.0f));
}

// Cox-de Boor p=3: values N[0..3], derivatives D[0..3] (already *p). No divides.
__device__ __forceinline__ void basis3(float u, int se, float* __restrict__ Nb,
                                       float* __restrict__ Db) {
    int   ci[6];
    float kn[6];
#pragma unroll
    for (int t = 0; t < 6; ++t) {
        int c = se - 2 + t;
        c = c < 0 ? 0 : (c > 29 ? 29 : c);
        ci[t] = c;
        kn[t] = (float)c * (1.0f / 29.0f);
    }
    float left[4], right[4];
    float ndu[4][4];
    ndu[0][0] = 1.0f;
#pragma unroll
    for (int j = 1; j <= 3; ++j) {
        left[j]  = u - kn[3 - j];
        right[j] = kn[j + 2] - u;
        float saved = 0.0f;
#pragma unroll
        for (int r = 0; r < j; ++r) {
            float tmp = ndu[r][j - 1] * rcp29(ci[r + 3] - ci[r + 3 - j]);
            ndu[r][j] = saved + right[r + 1] * tmp;
            saved = left[j - r] * tmp;
        }
        ndu[j][j] = saved;
    }
    Nb[0] = ndu[0][3]; Nb[1] = ndu[1][3]; Nb[2] = ndu[2][3]; Nb[3] = ndu[3][3];
    float t0 = ndu[0][2] * rcp29(ci[3] - ci[0]);
    float t1 = ndu[1][2] * rcp29(ci[4] - ci[1]);
    float t2 = ndu[2][2] * rcp29(ci[5] - ci[2]);
    Db[0] = -3.0f * t0;
    Db[1] = 3.0f * (t0 - t1);
    Db[2] = 3.0f * (t1 - t2);
    Db[3] = 3.0f * t2;
}

extern "C" __global__ void __launch_bounds__(NTHREADS, 1)
nurbs_surface_kernel(const float2* __restrict__ ep,
                     const float*  __restrict__ cp,
                     float4* __restrict__ out,
                     int n)
{
    extern __shared__ float4 tab[];   // [1024 cells][8 bank-columns]
    const int tid   = threadIdx.x;
    const int lane8 = tid & 7;

    for (int e = tid; e < NCP * NCP * 8; e += NTHREADS) {
        int cell = e >> 3;
        tab[e] = make_float4(cp[3 * cell + 0], cp[3 * cell + 1], cp[3 * cell + 2], 1.0f);
    }
    __syncthreads();

    float4* __restrict__ outn = out + n;
    const int stride = NBLOCKS * NTHREADS;
    int idx = blockIdx.x * NTHREADS + tid;
    if (idx >= n) return;

    float2 uv = ep[idx];                     // prologue load

    while (true) {
        float u = uv.x, v = uv.y;

        int se = (int)floorf(u * 29.0f);
        se = se < 0 ? 0 : (se > 28 ? 28 : se);
        int sn = (int)floorf(v * 29.0f);
        sn = sn < 0 ? 0 : (sn > 28 ? 28 : sn);

        // prefetch next uv (off the critical path; consumed next iteration)
        int nidx = idx + stride;
        bool has_next = nidx < n;
        if (has_next) uv = ep[nidx];

        // ---- issue ALL 16 cell loads now (independent, conflict-free);
        //      the basis computation below hides their latency ----
        const float4* __restrict__ p = tab + ((se * NCP + sn) * 8 + lane8);
        float4 g[16];
#pragma unroll
        for (int r = 0; r < 4; ++r)
#pragma unroll
            for (int s = 0; s < 4; ++s)
                g[r * 4 + s] = p[(r * NCP + s) * 8];

        // ---- basis (pure register math, ~90 instr of latency cover) ----
        float Nu[4], Du[4], Nv[4], Dv[4];
        basis3(u, se, Nu, Du);
        basis3(v, sn, Nv, Dv);

        // ---- contraction: pure FMA burst on resident registers ----
        float px=0.f,py=0.f,pz=0.f;   // surface point (homogeneous w == 1)
        float ex=0.f,ey=0.f,ez=0.f;   // d/du
        float fx=0.f,fy=0.f,fz=0.f;   // d/dv
#pragma unroll
        for (int r = 0; r < 4; ++r) {
            float ax=0.f, ay=0.f, az=0.f;
            float bx=0.f, by=0.f, bz=0.f;
#pragma unroll
            for (int s = 0; s < 4; ++s) {
                float4 gc = g[r * 4 + s];
                float nv = Nv[s], dv = Dv[s];
                ax = fmaf(nv, gc.x, ax); ay = fmaf(nv, gc.y, ay); az = fmaf(nv, gc.z, az);
                bx = fmaf(dv, gc.x, bx); by = fmaf(dv, gc.y, by); bz = fmaf(dv, gc.z, bz);
            }
            float nu = Nu[r], du = Du[r];
            px = fmaf(nu, ax, px); py = fmaf(nu, ay, py); pz = fmaf(nu, az, pz);
            ex = fmaf(du, ax, ex); ey = fmaf(du, ay, ey); ez = fmaf(du, az, ez);
            fx = fmaf(nu, bx, fx); fy = fmaf(nu, by, fy); fz = fmaf(nu, bz, fz);
        }

        // normal = normalize(cross(d_e, d_n))
        float cx = ey * fz - ez * fy;
        float cy = ez * fx - ex * fz;
        float cz = ex * fy - ey * fx;
        float il = rsqrtf(cx * cx + cy * cy + cz * cz);

        out[idx]  = make_float4(px, py, pz, 1.0f);
        outn[idx] = make_float4(cx * il, cy * il, cz * il, 0.0f);

        if (!has_next) break;
        idx = nidx;
    }
}

extern "C" void kernel_launch(void* const* d_in, const int* in_sizes, int n_in,
                              void* d_out, int out_size)
{
    const float2* ep = (const float2*)d_in[0];   // evaluation_points (N,2)
    const float*  cp = (const float*)d_in[1];    // control_points (32,32,3)
    int n = in_sizes[0] / 2;
    float4* out = (float4*)d_out;

    cudaFuncSetAttribute(nurbs_surface_kernel,
                         cudaFuncAttributeMaxDynamicSharedMemorySize, TAB_BYTES);

    nurbs_surface_kernel<<<NBLOCKS, NTHREADS, TAB_BYTES>>>(ep, cp, out, n);
}

// round 14
// speedup vs baseline: 1.2007x; 1.2007x over previous
#include <cuda_runtime.h>

// NURBS surface eval: DEG=3, N_CP=32x32, N_EVAL=2,000,000.
// Clamped-uniform knots: knot(i) = clamp(i-3,0,29)/29, span = floor(u*29)+3.
// Output: d_out[0..4N) = points (x,y,z,1); d_out[4N..8N) = normals (nx,ny,nz,0).
//
// R13 = R5 champion (persistent 148x1024, 8x bank-column-replicated smem table
// -> zero LDS conflicts, separable contraction, w==1) with the basis slimmed:
//  * closed-form reciprocal denominators: j=1 spacing is ALWAYS 1 knot
//    (reciprocal 29, constant); the 5 remaining reciprocals are 1-2 SELs off
//    se==0/1/27/28 predicates. No integer knot array, no generic select chain.
//  * 4 float FMNMX knot clamps (the only knots that can clamp).
//  * j=3 quotients t0..t2 reused directly as the derivative ingredients.
// ~285 issued instructions/point vs R5's ~380, identical memory behavior.

#define NCP 32
#define NTHREADS 1024
#define NBLOCKS 148
#define TAB_BYTES (NCP * NCP * 8 * 16)   // 128 KB

// Cox-de Boor p=3 (clamped-uniform knots), fully unrolled, no divides/MUFU.
// se in [0,28]; outputs basis N[0..3] and derivatives D[0..3] (already *p).
__device__ __forceinline__ void basis3(float u, int se,
                                       float* __restrict__ Nb, float* __restrict__ Db) {
    const float C  = 1.0f / 29.0f;
    const float R1 = 29.0f, R2 = 14.5f, R3 = 29.0f / 3.0f;
    float sef = (float)se;

    // local knots; only 4 can actually clamp
    float k0  = sef * C;
    float k1  = fmaf(1.0f, C, k0);                    // (se+1)/29, never clamps
    float km1 = fmaxf(k0 - C, 0.0f);
    float km2 = fmaxf(fmaf(-2.0f, C, k0), 0.0f);
    float k2  = fminf(fmaf(2.0f, C, k0), 1.0f);
    float k3  = fminf(fmaf(3.0f, C, k0), 1.0f);

    float l1 = u - k0, l2 = u - km1, l3 = u - km2;
    float r1 = k1 - u, r2 = k2 - u, r3 = k3 - u;

    // reciprocals of the integer knot-span widths (in units of 1/29):
    bool se0 = (se == 0), se1 = (se == 1), se27 = (se == 27), se28 = (se == 28);
    float i20 = se0  ? R1 : R2;                 // j=2, r=0
    float i21 = se28 ? R1 : R2;                 // j=2, r=1
    float i30 = se0  ? R1 : (se1 ? R2 : R3);    // j=3, r=0
    float i31 = (se0 || se28) ? R2 : R3;        // j=3, r=1
    float i32 = se28 ? R1 : (se27 ? R2 : R3);   // j=3, r=2

    // j=1 (den always 1/29)
    float n01 = r1 * R1;
    float n11 = l1 * R1;
    // j=2
    float q20 = n01 * i20;
    float n02 = r1 * q20;
    float s2  = l2 * q20;
    float q21 = n11 * i21;
    float n12 = fmaf(r2, q21, s2);
    float n22 = l1 * q21;
    // j=3 (quotients are exactly the derivative t_r values)
    float t0 = n02 * i30;
    Nb[0] = r1 * t0;
    float s3 = l3 * t0;
    float t1 = n12 * i31;
    Nb[1] = fmaf(r2, t1, s3);
    s3 = l2 * t1;
    float t2 = n22 * i32;
    Nb[2] = fmaf(r3, t2, s3);
    Nb[3] = l1 * t2;

    Db[0] = -3.0f * t0;
    Db[1] = 3.0f * (t0 - t1);
    Db[2] = 3.0f * (t1 - t2);
    Db[3] = 3.0f * t2;
}

extern "C" __global__ void __launch_bounds__(NTHREADS, 1)
nurbs_surface_kernel(const float2* __restrict__ ep,
                     const float*  __restrict__ cp,
                     float4* __restrict__ out,
                     int n)
{
    extern __shared__ float4 tab[];   // [1024 cells][8 bank-columns]
    const int tid   = threadIdx.x;
    const int lane8 = tid & 7;

#pragma unroll
    for (int i = 0; i < 8; ++i) {
        int e = i * NTHREADS + tid;
        int cell = e >> 3;
        tab[e] = make_float4(cp[3 * cell + 0], cp[3 * cell + 1], cp[3 * cell + 2], 1.0f);
    }
    __syncthreads();

    float4* __restrict__ outn = out + n;

    for (int idx = blockIdx.x * NTHREADS + tid; idx < n; idx += NBLOCKS * NTHREADS) {
        float2 uv = ep[idx];

        int se = (int)floorf(uv.x * 29.0f);
        se = se < 0 ? 0 : (se > 28 ? 28 : se);
        int sn = (int)floorf(uv.y * 29.0f);
        sn = sn < 0 ? 0 : (sn > 28 ? 28 : sn);

        float Nu[4], Du[4], Nv[4], Dv[4];
        basis3(uv.x, se, Nu, Du);
        basis3(uv.y, sn, Nv, Dv);

        // Conflict-free gather base: this lane's private bank column.
        const float4* __restrict__ p = tab + ((se * NCP + sn) * 8 + lane8);

        float px=0.f,py=0.f,pz=0.f;   // surface point (homogeneous w == 1)
        float ex=0.f,ey=0.f,ez=0.f;   // d/du
        float fx=0.f,fy=0.f,fz=0.f;   // d/dv
#pragma unroll
        for (int r = 0; r < 4; ++r) {
            float ax=0.f, ay=0.f, az=0.f;
            float bx=0.f, by=0.f, bz=0.f;
#pragma unroll
            for (int s = 0; s < 4; ++s) {
                float4 g = p[(r * NCP + s) * 8];
                float nv = Nv[s], dv = Dv[s];
                ax = fmaf(nv, g.x, ax); ay = fmaf(nv, g.y, ay); az = fmaf(nv, g.z, az);
                bx = fmaf(dv, g.x, bx); by = fmaf(dv, g.y, by); bz = fmaf(dv, g.z, bz);
            }
            float nu = Nu[r], du = Du[r];
            px = fmaf(nu, ax, px); py = fmaf(nu, ay, py); pz = fmaf(nu, az, pz);
            ex = fmaf(du, ax, ex); ey = fmaf(du, ay, ey); ez = fmaf(du, az, ez);
            fx = fmaf(nu, bx, fx); fy = fmaf(nu, by, fy); fz = fmaf(nu, bz, fz);
        }

        // normal = normalize(cross(d_e, d_n))
        float cx = ey * fz - ez * fy;
        float cy = ez * fx - ex * fz;
        float cz = ex * fy - ey * fx;
        float il = rsqrtf(cx * cx + cy * cy + cz * cz);

        out[idx]  = make_float4(px, py, pz, 1.0f);
        outn[idx] = make_float4(cx * il, cy * il, cz * il, 0.0f);
    }
}

extern "C" void kernel_launch(void* const* d_in, const int* in_sizes, int n_in,
                              void* d_out, int out_size)
{
    const float2* ep = (const float2*)d_in[0];   // evaluation_points (N,2)
    const float*  cp = (const float*)d_in[1];    // control_points (32,32,3)
    int n = in_sizes[0] / 2;
    float4* out = (float4*)d_out;

    cudaFuncSetAttribute(nurbs_surface_kernel,
                         cudaFuncAttributeMaxDynamicSharedMemorySize, TAB_BYTES);

    nurbs_surface_kernel<<<NBLOCKS, NTHREADS, TAB_BYTES>>>(ep, cp, out, n);
}